// round 1
// baseline (speedup 1.0000x reference)
#include <cuda_runtime.h>
#include <math.h>

// Problem constants
#define BB 8
#define LL 1024
#define DD 1024
#define KK 128
#define TROWS 1000
#define SCALING 0.08838834764831845f   // 128^-0.5

// ---------------- scratch (device globals; no allocation allowed) ----------
__device__ float g_h[TROWS * DD];      // silu(time_table @ W1 + b1)
__device__ float g_tmlp[TROWS * DD];   // g_h @ W2 + b2
__device__ float g_v[DD];              // pos_emb_w @ pos_feature_w
__device__ float g_s[BB * LL];         // per-(b,l) attention scalar

// ---------------- GEMM: C[M,1024] = A[M,1024] @ B[1024,1024] + bias --------
// BM=64, BN=128, BK=16, 256 threads, 4x8 microtile per thread.
// stage==0: A=Aparam (time_table), C=g_h, apply SiLU
// stage==1: A=g_h,                 C=g_tmlp, no SiLU
__global__ void gemm_bias_kernel(const float* __restrict__ Aparam,
                                 const float* __restrict__ B,
                                 const float* __restrict__ bias,
                                 int M, int stage)
{
    const int Nw = 1024, Kd = 1024;
    const float* A = (stage == 0) ? Aparam : g_h;
    float* C = (stage == 0) ? g_h : g_tmlp;

    __shared__ float As[16 * 64];    // [k][m]
    __shared__ float Bs[16 * 128];   // [k][n]

    int tid = threadIdx.x;
    int tx = tid & 15, ty = tid >> 4;
    int m0 = blockIdx.y * 64;
    int n0 = blockIdx.x * 128;

    float acc[4][8];
#pragma unroll
    for (int i = 0; i < 4; i++)
#pragma unroll
        for (int j = 0; j < 8; j++) acc[i][j] = 0.f;

    int a_row = tid >> 2;
    int a_k4 = (tid & 3) * 4;

    for (int k0 = 0; k0 < Kd; k0 += 16) {
        // load A tile 64x16 (guarded on M)
        float4 av = make_float4(0.f, 0.f, 0.f, 0.f);
        int gr = m0 + a_row;
        if (gr < M) av = *(const float4*)(A + (size_t)gr * Kd + k0 + a_k4);
        As[(a_k4 + 0) * 64 + a_row] = av.x;
        As[(a_k4 + 1) * 64 + a_row] = av.y;
        As[(a_k4 + 2) * 64 + a_row] = av.z;
        As[(a_k4 + 3) * 64 + a_row] = av.w;
        // load B tile 16x128: two float4 per thread
        {
            int f = tid;
            int r = f >> 5, c4 = (f & 31) * 4;
            *(float4*)(Bs + r * 128 + c4) =
                *(const float4*)(B + (size_t)(k0 + r) * Nw + n0 + c4);
            f = tid + 256;
            r = f >> 5; c4 = (f & 31) * 4;
            *(float4*)(Bs + r * 128 + c4) =
                *(const float4*)(B + (size_t)(k0 + r) * Nw + n0 + c4);
        }
        __syncthreads();
#pragma unroll
        for (int k = 0; k < 16; k++) {
            float4 a = *(const float4*)(As + k * 64 + ty * 4);
            float4 b0 = *(const float4*)(Bs + k * 128 + tx * 8);
            float4 b1 = *(const float4*)(Bs + k * 128 + tx * 8 + 4);
            float av4[4] = {a.x, a.y, a.z, a.w};
            float bv[8] = {b0.x, b0.y, b0.z, b0.w, b1.x, b1.y, b1.z, b1.w};
#pragma unroll
            for (int i = 0; i < 4; i++)
#pragma unroll
                for (int j = 0; j < 8; j++)
                    acc[i][j] += av4[i] * bv[j];
        }
        __syncthreads();
    }

#pragma unroll
    for (int i = 0; i < 4; i++) {
        int gr = m0 + ty * 4 + i;
        if (gr >= M) continue;
#pragma unroll
        for (int j = 0; j < 8; j++) {
            int gc = n0 + tx * 8 + j;
            float vv = acc[i][j] + bias[gc];
            if (stage == 0) vv = vv / (1.0f + __expf(-vv));   // SiLU
            C[(size_t)gr * Nw + gc] = vv;
        }
    }
}

// ---------------- v[d] = sum_k pos_emb_w[k] * pos_feature_w[k,d] -----------
__global__ void v_kernel(const float* __restrict__ pew,
                         const float* __restrict__ pfw)
{
    int d = blockIdx.x * blockDim.x + threadIdx.x;
    if (d < DD) {
        float acc = 0.f;
#pragma unroll 8
        for (int k = 0; k < KK; k++)
            acc += pew[k] * pfw[k * DD + d];
        g_v[d] = acc;
    }
}

// ---------------- s[b,i] = softmax_j(SCALING/(r_ij+1)) . r_j (masked) ------
// grid = B*128 blocks; each block: 8 queries (1 per warp), whole batch in smem
__global__ void s_kernel(const float* __restrict__ pos,
                         const int* __restrict__ token)
{
    __shared__ float px[LL], py[LL], pz[LL], rr[LL], mm[LL];
    int b = blockIdx.x >> 7;
    int q0 = (blockIdx.x & 127) * 8;
    int tid = threadIdx.x;

    for (int j = tid; j < LL; j += 256) {
        float x = pos[(size_t)(b * LL + j) * 3 + 0];
        float y = pos[(size_t)(b * LL + j) * 3 + 1];
        float z = pos[(size_t)(b * LL + j) * 3 + 2];
        px[j] = x; py[j] = y; pz[j] = z;
        rr[j] = sqrtf(x * x + y * y + z * z);
        mm[j] = (token[b * LL + j] != 0) ? 1.0f : 0.0f;
    }
    __syncthreads();

    int w = tid >> 5, lane = tid & 31;
    int q = q0 + w;
    float qx = px[q], qy = py[q], qz = pz[q];
    float se = 0.f, sr = 0.f;
#pragma unroll 4
    for (int j = lane; j < LL; j += 32) {
        float dx = px[j] - qx, dy = py[j] - qy, dz = pz[j] - qz;
        float d = sqrtf(dx * dx + dy * dy + dz * dz);
        float wt = __expf(SCALING / (d + 1.0f)) * mm[j];  // masked keys -> exp(NEG)=0
        se += wt;
        sr += wt * rr[j];
    }
#pragma unroll
    for (int o = 16; o > 0; o >>= 1) {
        se += __shfl_xor_sync(0xffffffffu, se, o);
        sr += __shfl_xor_sync(0xffffffffu, sr, o);
    }
    if (lane == 0)
        g_s[b * LL + q] = (mm[q] != 0.f) ? (sr / se) : 0.0f;
}

// ---------------- fused epilogue over [B,L,D] -------------------------------
// out = embed[tok] + ismol*sum_j atom[idx_j] + tmlp[ts] + (!pad)*s*v
__global__ void epilogue_kernel(const int* __restrict__ token,
                                const int* __restrict__ node_attr,
                                const int* __restrict__ ismol,
                                const int* __restrict__ tstep,
                                const float* __restrict__ embed,
                                const float* __restrict__ atab,
                                float* __restrict__ out)
{
    __shared__ int sidx[8];
    __shared__ int stok, sts, smol;
    __shared__ float ss;
    int bl = blockIdx.x;                 // 0..8191
    int b = bl >> 10;
    int tid = threadIdx.x;
    if (tid < 8) sidx[tid] = node_attr[bl * 9 + 1 + tid];
    else if (tid == 8) stok = token[bl];
    else if (tid == 9) sts = tstep[bl];
    else if (tid == 10) smol = ismol[b];
    else if (tid == 11) ss = g_s[bl];
    __syncthreads();

    int d = tid * 4;
    float4 acc = *(const float4*)(embed + (size_t)stok * DD + d);
    float4 t4 = *(const float4*)(g_tmlp + (size_t)sts * DD + d);
    acc.x += t4.x; acc.y += t4.y; acc.z += t4.z; acc.w += t4.w;
    if (smol) {
#pragma unroll
        for (int j = 0; j < 8; j++) {
            float4 a4 = *(const float4*)(atab + (size_t)sidx[j] * DD + d);
            acc.x += a4.x; acc.y += a4.y; acc.z += a4.z; acc.w += a4.w;
        }
    }
    if (stok != 0) {
        float4 v4 = *(const float4*)(g_v + d);
        float s = ss;
        acc.x += s * v4.x; acc.y += s * v4.y; acc.z += s * v4.z; acc.w += s * v4.w;
    }
    *(float4*)(out + (size_t)bl * DD + d) = acc;
}

// ---------------- padding mask tail (if harness expects tuple output) ------
__global__ void mask_kernel(const int* __restrict__ token, float* __restrict__ out)
{
    int i = blockIdx.x * blockDim.x + threadIdx.x;
    if (i < BB * LL)
        out[(size_t)BB * LL * DD + i] = (token[i] == 0) ? 1.0f : 0.0f;
}

// ---------------------------------------------------------------------------
extern "C" void kernel_launch(void* const* d_in, const int* in_sizes, int n_in,
                              void* d_out, int out_size)
{
    const int*   token     = (const int*)d_in[0];
    const int*   node_attr = (const int*)d_in[1];
    const int*   ismol     = (const int*)d_in[2];   // bool -> int32 per harness dtype contract
    const float* pos       = (const float*)d_in[3];
    const int*   tstep     = (const int*)d_in[4];
    const float* embed     = (const float*)d_in[5];
    const float* atab      = (const float*)d_in[6];
    const float* ttab      = (const float*)d_in[7];
    const float* w1        = (const float*)d_in[8];
    const float* b1        = (const float*)d_in[9];
    const float* w2        = (const float*)d_in[10];
    const float* b2        = (const float*)d_in[11];
    const float* pew       = (const float*)d_in[12];
    const float* pfw       = (const float*)d_in[13];
    float* out = (float*)d_out;

    // time MLP on the 1000 unique timestep rows
    dim3 ggrid(1024 / 128, (TROWS + 63) / 64);
    gemm_bias_kernel<<<ggrid, 256>>>(ttab, w1, b1, TROWS, 0);
    gemm_bias_kernel<<<ggrid, 256>>>(nullptr, w2, b2, TROWS, 1);

    // rank-1 collapsed positional attention
    v_kernel<<<(DD + 255) / 256, 256>>>(pew, pfw);
    s_kernel<<<BB * 128, 256>>>(pos, token);

    // fused gather + add epilogue
    epilogue_kernel<<<BB * LL, 256>>>(token, node_attr, ismol, tstep,
                                      embed, atab, out);

    // padding_mask tail if the output buffer includes it
    if (out_size >= BB * LL * DD + BB * LL)
        mask_kernel<<<(BB * LL + 255) / 256, 256>>>(token, out);
}

// round 3
// speedup vs baseline: 2.0159x; 2.0159x over previous
#include <cuda_runtime.h>
#include <cuda_bf16.h>
#include <math.h>
#include <stdint.h>

// Problem constants
#define BB 8
#define LL 1024
#define DD 1024
#define KK 128
#define TROWS 1000
#define MPAD 1024
#define SCALING 0.08838834764831845f   // 128^-0.5

// ---------------- device scratch (no allocation allowed) -------------------
__device__ __align__(16) __nv_bfloat16 g_A1hi[MPAD * DD];
__device__ __align__(16) __nv_bfloat16 g_A1lo[MPAD * DD];
__device__ __align__(16) __nv_bfloat16 g_Ahhi[MPAD * DD];
__device__ __align__(16) __nv_bfloat16 g_Ahlo[MPAD * DD];
__device__ __align__(16) __nv_bfloat16 g_Wt1hi[DD * DD];
__device__ __align__(16) __nv_bfloat16 g_Wt1lo[DD * DD];
__device__ __align__(16) __nv_bfloat16 g_Wt2hi[DD * DD];
__device__ __align__(16) __nv_bfloat16 g_Wt2lo[DD * DD];
__device__ __align__(16) float g_tmlp[MPAD * DD];
__device__ float g_v[DD];
__device__ float g_s[BB * LL];

// ---------------- small helpers --------------------------------------------
__device__ __forceinline__ uint32_t packbf2(__nv_bfloat16 a, __nv_bfloat16 b) {
    __nv_bfloat162 t; t.x = a; t.y = b;
    return *(uint32_t*)&t;
}
__device__ __forceinline__ void split32(float v, __nv_bfloat16& h, __nv_bfloat16& l) {
    h = __float2bfloat16(v);
    l = __float2bfloat16(v - __bfloat162float(h));
}
__device__ __forceinline__ void mma_bf16(float* c, uint32_t a0, uint32_t a1,
                                         uint32_t a2, uint32_t a3,
                                         uint32_t b0, uint32_t b1) {
    asm volatile(
        "mma.sync.aligned.m16n8k16.row.col.f32.bf16.bf16.f32 "
        "{%0,%1,%2,%3}, {%4,%5,%6,%7}, {%8,%9}, {%0,%1,%2,%3};"
        : "+f"(c[0]), "+f"(c[1]), "+f"(c[2]), "+f"(c[3])
        : "r"(a0), "r"(a1), "r"(a2), "r"(a3), "r"(b0), "r"(b1));
}

// ---------------- prep: time_table -> bf16 hi/lo (pad to 1024 rows) --------
__global__ void convA_kernel(const float* __restrict__ ttab)
{
    int m = blockIdx.x;
    int k = threadIdx.x * 4;
    float4 x = make_float4(0.f, 0.f, 0.f, 0.f);
    if (m < TROWS) x = *(const float4*)(ttab + (size_t)m * DD + k);
    __nv_bfloat16 h0, l0, h1, l1, h2, l2, h3, l3;
    split32(x.x, h0, l0); split32(x.y, h1, l1);
    split32(x.z, h2, l2); split32(x.w, h3, l3);
    uint2 hw = make_uint2(packbf2(h0, h1), packbf2(h2, h3));
    uint2 lw = make_uint2(packbf2(l0, l1), packbf2(l2, l3));
    *(uint2*)(g_A1hi + (size_t)m * DD + k) = hw;
    *(uint2*)(g_A1lo + (size_t)m * DD + k) = lw;
}

// ---------------- prep: W[K,N] -> Wt[N,K] bf16 hi/lo (transpose) -----------
__global__ void convW_kernel(const float* __restrict__ w1,
                             const float* __restrict__ w2)
{
    __shared__ float tile[32][33];
    int z = blockIdx.z;
    const float* W = z ? w2 : w1;
    __nv_bfloat16* Whi = z ? g_Wt2hi : g_Wt1hi;
    __nv_bfloat16* Wlo = z ? g_Wt2lo : g_Wt1lo;
    int n0 = blockIdx.x * 32, k0 = blockIdx.y * 32;
    int tx = threadIdx.x, ty = threadIdx.y;
#pragma unroll
    for (int i = 0; i < 4; i++)
        tile[ty + i * 8][tx] = W[(size_t)(k0 + ty + i * 8) * DD + n0 + tx];
    __syncthreads();
#pragma unroll
    for (int i = 0; i < 4; i++) {
        int n = n0 + ty + i * 8, k = k0 + tx;
        float v = tile[tx][ty + i * 8];
        __nv_bfloat16 h, l;
        split32(v, h, l);
        Whi[(size_t)n * DD + k] = h;
        Wlo[(size_t)n * DD + k] = l;
    }
}

// ---------------- mma.sync GEMM: C[1024,1024] = A @ W^T (+bias, opt SiLU) --
// CTA tile 128x64, K-chunk 32, double-buffered SMEM, 8 warps (4m x 2n),
// warp tile 32x32. 3 bf16 passes (hi*hi + hi*lo + lo*hi) ~= fp32.
// stage 0: A=g_A1{hi,lo}, B=g_Wt1, out=silu(.+b) -> g_Ah{hi,lo}
// stage 1: A=g_Ah{hi,lo}, B=g_Wt2, out fp32 (.+b) -> g_tmlp
#define PITCH 80            // bytes per 32-col bf16 row (64B data + 16B pad)
#define ST_SZ 30720         // one pipeline stage: Ahi,Alo(10240 ea) Bhi,Blo(5120 ea)
__global__ void __launch_bounds__(256, 1)
gemm_mma_kernel(const float* __restrict__ bias, int stage)
{
    extern __shared__ __align__(16) char smem[];

    const __nv_bfloat16* Ahi = stage ? g_Ahhi : g_A1hi;
    const __nv_bfloat16* Alo = stage ? g_Ahlo : g_A1lo;
    const __nv_bfloat16* Bhi = stage ? g_Wt2hi : g_Wt1hi;
    const __nv_bfloat16* Blo = stage ? g_Wt2lo : g_Wt1lo;

    const int tid = threadIdx.x;
    const int lane = tid & 31;
    const int wid = tid >> 5;
    const int wm = wid & 3;           // 4 warps along M
    const int wn = wid >> 2;          // 2 warps along N
    const int m0 = blockIdx.y * 128;
    const int n0 = blockIdx.x * 64;

    float acc[2][4][4];
#pragma unroll
    for (int i = 0; i < 2; i++)
#pragma unroll
        for (int j = 0; j < 4; j++)
#pragma unroll
            for (int q = 0; q < 4; q++) acc[i][j][q] = 0.f;

    // ---- loader lambda-equivalent (macro-free, inlined twice) ----
    // chunk c -> buffer (c & 1)
#define LOAD_CHUNK(c_)                                                          \
    do {                                                                        \
        char* st = smem + ((c_) & 1) * ST_SZ;                                   \
        int k0 = (c_) * 32;                                                     \
        _Pragma("unroll")                                                       \
        for (int idx = tid; idx < 512; idx += 256) {                            \
            int r = idx >> 2, q = idx & 3;                                      \
            size_t g = (size_t)(m0 + r) * DD + k0 + q * 8;                      \
            *(uint4*)(st + r * PITCH + q * 16)         = *(const uint4*)(Ahi + g); \
            *(uint4*)(st + 10240 + r * PITCH + q * 16) = *(const uint4*)(Alo + g); \
        }                                                                       \
        _Pragma("unroll")                                                       \
        for (int idx = tid; idx < 256; idx += 256) {                            \
            int r = idx >> 2, q = idx & 3;                                      \
            size_t g = (size_t)(n0 + r) * DD + k0 + q * 8;                      \
            *(uint4*)(st + 20480 + r * PITCH + q * 16) = *(const uint4*)(Bhi + g); \
            *(uint4*)(st + 25600 + r * PITCH + q * 16) = *(const uint4*)(Blo + g); \
        }                                                                       \
    } while (0)

    LOAD_CHUNK(0);
    __syncthreads();

    for (int c = 0; c < 32; c++) {
        if (c + 1 < 32) LOAD_CHUNK(c + 1);
        const char* st = smem + (c & 1) * ST_SZ;
        const char* sAh = st;
        const char* sAl = st + 10240;
        const char* sBh = st + 20480;
        const char* sBl = st + 25600;

#pragma unroll
        for (int kk = 0; kk < 32; kk += 16) {
            const int cb = (kk + (lane & 3) * 2) * 2;   // byte offset in row
            uint32_t ah[2][4], al[2][4], bh[4][2], bl[4][2];
#pragma unroll
            for (int mf = 0; mf < 2; mf++) {
                int r = wm * 32 + mf * 16 + (lane >> 2);
                ah[mf][0] = *(const uint32_t*)(sAh + r * PITCH + cb);
                ah[mf][1] = *(const uint32_t*)(sAh + (r + 8) * PITCH + cb);
                ah[mf][2] = *(const uint32_t*)(sAh + r * PITCH + cb + 16);
                ah[mf][3] = *(const uint32_t*)(sAh + (r + 8) * PITCH + cb + 16);
                al[mf][0] = *(const uint32_t*)(sAl + r * PITCH + cb);
                al[mf][1] = *(const uint32_t*)(sAl + (r + 8) * PITCH + cb);
                al[mf][2] = *(const uint32_t*)(sAl + r * PITCH + cb + 16);
                al[mf][3] = *(const uint32_t*)(sAl + (r + 8) * PITCH + cb + 16);
            }
#pragma unroll
            for (int nf = 0; nf < 4; nf++) {
                int n = wn * 32 + nf * 8 + (lane >> 2);
                bh[nf][0] = *(const uint32_t*)(sBh + n * PITCH + cb);
                bh[nf][1] = *(const uint32_t*)(sBh + n * PITCH + cb + 16);
                bl[nf][0] = *(const uint32_t*)(sBl + n * PITCH + cb);
                bl[nf][1] = *(const uint32_t*)(sBl + n * PITCH + cb + 16);
            }
#pragma unroll
            for (int mf = 0; mf < 2; mf++)
#pragma unroll
                for (int nf = 0; nf < 4; nf++) {
                    mma_bf16(acc[mf][nf], ah[mf][0], ah[mf][1], ah[mf][2], ah[mf][3],
                             bh[nf][0], bh[nf][1]);
                    mma_bf16(acc[mf][nf], ah[mf][0], ah[mf][1], ah[mf][2], ah[mf][3],
                             bl[nf][0], bl[nf][1]);
                    mma_bf16(acc[mf][nf], al[mf][0], al[mf][1], al[mf][2], al[mf][3],
                             bh[nf][0], bh[nf][1]);
                }
        }
        __syncthreads();
    }

    // ---- epilogue: bias (+SiLU+split for stage 0) ----
#pragma unroll
    for (int mf = 0; mf < 2; mf++) {
#pragma unroll
        for (int nf = 0; nf < 4; nf++) {
            int col = n0 + wn * 32 + nf * 8 + (lane & 3) * 2;
            float2 bb = *(const float2*)(bias + col);
            int r0 = m0 + wm * 32 + mf * 16 + (lane >> 2);
#pragma unroll
            for (int half = 0; half < 2; half++) {
                int r = r0 + half * 8;
                float v0 = acc[mf][nf][2 * half + 0] + bb.x;
                float v1 = acc[mf][nf][2 * half + 1] + bb.y;
                if (stage == 0) {
                    v0 = __fdividef(v0, 1.0f + __expf(-v0));
                    v1 = __fdividef(v1, 1.0f + __expf(-v1));
                    __nv_bfloat16 h0, l0, h1, l1;
                    split32(v0, h0, l0);
                    split32(v1, h1, l1);
                    *(uint32_t*)(g_Ahhi + (size_t)r * DD + col) = packbf2(h0, h1);
                    *(uint32_t*)(g_Ahlo + (size_t)r * DD + col) = packbf2(l0, l1);
                } else {
                    *(float2*)(g_tmlp + (size_t)r * DD + col) = make_float2(v0, v1);
                }
            }
        }
    }
}

// ---------------- v[d] = sum_k pos_emb_w[k] * pos_feature_w[k,d] -----------
__global__ void v_kernel(const float* __restrict__ pew,
                         const float* __restrict__ pfw)
{
    int d = blockIdx.x * blockDim.x + threadIdx.x;
    if (d < DD) {
        float acc = 0.f;
#pragma unroll 8
        for (int k = 0; k < KK; k++)
            acc += pew[k] * pfw[k * DD + d];
        g_v[d] = acc;
    }
}

// ---------------- s[b,i] = softmax_j(SCALING/(r_ij+1)) . r_j (masked) ------
__global__ void s_kernel(const float* __restrict__ pos,
                         const int* __restrict__ token)
{
    __shared__ float px[LL], py[LL], pz[LL], rr[LL], mm[LL];
    int b = blockIdx.x >> 7;
    int q0 = (blockIdx.x & 127) * 8;
    int tid = threadIdx.x;

    for (int j = tid; j < LL; j += 256) {
        float x = pos[(size_t)(b * LL + j) * 3 + 0];
        float y = pos[(size_t)(b * LL + j) * 3 + 1];
        float z = pos[(size_t)(b * LL + j) * 3 + 2];
        px[j] = x; py[j] = y; pz[j] = z;
        float n2 = x * x + y * y + z * z;
        rr[j] = n2 * rsqrtf(fmaxf(n2, 1e-36f));
        mm[j] = (token[b * LL + j] != 0) ? 1.0f : 0.0f;
    }
    __syncthreads();

    int w = tid >> 5, lane = tid & 31;
    int q = q0 + w;
    float qx = px[q], qy = py[q], qz = pz[q];
    float se = 0.f, sr = 0.f;
#pragma unroll 4
    for (int j = lane; j < LL; j += 32) {
        float dx = px[j] - qx, dy = py[j] - qy, dz = pz[j] - qz;
        float n2 = dx * dx + dy * dy + dz * dz;
        float d = n2 * rsqrtf(fmaxf(n2, 1e-36f));
        float wt = __expf(__fdividef(SCALING, d + 1.0f)) * mm[j];
        se += wt;
        sr += wt * rr[j];
    }
#pragma unroll
    for (int o = 16; o > 0; o >>= 1) {
        se += __shfl_xor_sync(0xffffffffu, se, o);
        sr += __shfl_xor_sync(0xffffffffu, sr, o);
    }
    if (lane == 0)
        g_s[b * LL + q] = (mm[q] != 0.f) ? (sr / se) : 0.0f;
}

// ---------------- fused epilogue over [B,L,D] -------------------------------
__global__ void epilogue_kernel(const int* __restrict__ token,
                                const int* __restrict__ node_attr,
                                const int* __restrict__ ismol,
                                const int* __restrict__ tstep,
                                const float* __restrict__ embed,
                                const float* __restrict__ atab,
                                float* __restrict__ out)
{
    __shared__ int sidx[8];
    __shared__ int stok, sts, smol;
    __shared__ float ss;
    int bl = blockIdx.x;
    int b = bl >> 10;
    int tid = threadIdx.x;
    if (tid < 8) sidx[tid] = node_attr[bl * 9 + 1 + tid];
    else if (tid == 8) stok = token[bl];
    else if (tid == 9) sts = tstep[bl];
    else if (tid == 10) smol = ismol[b];
    else if (tid == 11) ss = g_s[bl];
    __syncthreads();

    int d = tid * 4;
    float4 acc = *(const float4*)(embed + (size_t)stok * DD + d);
    float4 t4 = *(const float4*)(g_tmlp + (size_t)sts * DD + d);
    acc.x += t4.x; acc.y += t4.y; acc.z += t4.z; acc.w += t4.w;
    if (smol) {
#pragma unroll
        for (int j = 0; j < 8; j++) {
            float4 a4 = *(const float4*)(atab + (size_t)sidx[j] * DD + d);
            acc.x += a4.x; acc.y += a4.y; acc.z += a4.z; acc.w += a4.w;
        }
    }
    if (stok != 0) {
        float4 v4 = *(const float4*)(g_v + d);
        float s = ss;
        acc.x += s * v4.x; acc.y += s * v4.y; acc.z += s * v4.z; acc.w += s * v4.w;
    }
    *(float4*)(out + (size_t)bl * DD + d) = acc;
}

// ---------------- padding mask tail -----------------------------------------
__global__ void mask_kernel(const int* __restrict__ token, float* __restrict__ out)
{
    int i = blockIdx.x * blockDim.x + threadIdx.x;
    if (i < BB * LL)
        out[(size_t)BB * LL * DD + i] = (token[i] == 0) ? 1.0f : 0.0f;
}

// ---------------------------------------------------------------------------
extern "C" void kernel_launch(void* const* d_in, const int* in_sizes, int n_in,
                              void* d_out, int out_size)
{
    const int*   token     = (const int*)d_in[0];
    const int*   node_attr = (const int*)d_in[1];
    const int*   ismol     = (const int*)d_in[2];
    const float* pos       = (const float*)d_in[3];
    const int*   tstep     = (const int*)d_in[4];
    const float* embed     = (const float*)d_in[5];
    const float* atab      = (const float*)d_in[6];
    const float* ttab      = (const float*)d_in[7];
    const float* w1        = (const float*)d_in[8];
    const float* b1        = (const float*)d_in[9];
    const float* w2        = (const float*)d_in[10];
    const float* b2        = (const float*)d_in[11];
    const float* pew       = (const float*)d_in[12];
    const float* pfw       = (const float*)d_in[13];
    float* out = (float*)d_out;

    const int DSMEM = 2 * ST_SZ;   // 61440 bytes
    cudaFuncSetAttribute(gemm_mma_kernel,
                         cudaFuncAttributeMaxDynamicSharedMemorySize, DSMEM);

    // independent small kernels
    v_kernel<<<(DD + 255) / 256, 256>>>(pew, pfw);
    s_kernel<<<BB * 128, 256>>>(pos, token);

    // bf16 hi/lo conversions
    convA_kernel<<<MPAD, 256>>>(ttab);
    convW_kernel<<<dim3(32, 32, 2), dim3(32, 8)>>>(w1, w2);

    // time MLP via mma.sync bf16 hi/lo split (fp32 accumulate)
    gemm_mma_kernel<<<dim3(16, 8), 256, DSMEM>>>(b1, 0);
    gemm_mma_kernel<<<dim3(16, 8), 256, DSMEM>>>(b2, 1);

    // fused gather + add epilogue
    epilogue_kernel<<<BB * LL, 256>>>(token, node_attr, ismol, tstep,
                                      embed, atab, out);

    if (out_size >= BB * LL * DD + BB * LL)
        mask_kernel<<<(BB * LL + 255) / 256, 256>>>(token, out);
}

// round 4
// speedup vs baseline: 2.0770x; 1.0303x over previous
#include <cuda_runtime.h>
#include <cuda_bf16.h>
#include <math.h>
#include <stdint.h>

// Problem constants
#define BB 8
#define LL 1024
#define DD 1024
#define KK 128
#define TROWS 1000
#define MPAD 1024
#define SCALING 0.08838834764831845f   // 128^-0.5

// ---------------- device scratch (no allocation allowed) -------------------
__device__ __align__(16) __nv_bfloat16 g_A1hi[MPAD * DD];
__device__ __align__(16) __nv_bfloat16 g_A1lo[MPAD * DD];
__device__ __align__(16) __nv_bfloat16 g_Ahhi[MPAD * DD];
__device__ __align__(16) __nv_bfloat16 g_Ahlo[MPAD * DD];
__device__ __align__(16) __nv_bfloat16 g_Wt1hi[DD * DD];
__device__ __align__(16) __nv_bfloat16 g_Wt1lo[DD * DD];
__device__ __align__(16) __nv_bfloat16 g_Wt2hi[DD * DD];
__device__ __align__(16) __nv_bfloat16 g_Wt2lo[DD * DD];
__device__ __align__(16) float g_tmlp[MPAD * DD];
__device__ float g_v[DD];
__device__ float g_s[BB * LL];

// ---------------- small helpers --------------------------------------------
__device__ __forceinline__ uint32_t packbf2(__nv_bfloat16 a, __nv_bfloat16 b) {
    __nv_bfloat162 t; t.x = a; t.y = b;
    return *(uint32_t*)&t;
}
__device__ __forceinline__ void split32(float v, __nv_bfloat16& h, __nv_bfloat16& l) {
    h = __float2bfloat16(v);
    l = __float2bfloat16(v - __bfloat162float(h));
}
__device__ __forceinline__ void mma_bf16(float* c, const uint32_t* a,
                                         uint32_t b0, uint32_t b1) {
    asm volatile(
        "mma.sync.aligned.m16n8k16.row.col.f32.bf16.bf16.f32 "
        "{%0,%1,%2,%3}, {%4,%5,%6,%7}, {%8,%9}, {%0,%1,%2,%3};"
        : "+f"(c[0]), "+f"(c[1]), "+f"(c[2]), "+f"(c[3])
        : "r"(a[0]), "r"(a[1]), "r"(a[2]), "r"(a[3]), "r"(b0), "r"(b1));
}
__device__ __forceinline__ void ldsm_x4(uint32_t* r, uint32_t addr) {
    asm volatile("ldmatrix.sync.aligned.m8n8.x4.shared.b16 {%0,%1,%2,%3}, [%4];"
                 : "=r"(r[0]), "=r"(r[1]), "=r"(r[2]), "=r"(r[3]) : "r"(addr));
}
__device__ __forceinline__ void ldsm_x4_t(uint32_t* r, uint32_t addr) {
    asm volatile("ldmatrix.sync.aligned.m8n8.x4.trans.shared.b16 {%0,%1,%2,%3}, [%4];"
                 : "=r"(r[0]), "=r"(r[1]), "=r"(r[2]), "=r"(r[3]) : "r"(addr));
}

// ---------------- prep: time_table -> bf16 hi/lo (pad to 1024 rows) --------
__global__ void convA_kernel(const float* __restrict__ ttab)
{
    int m = blockIdx.x;
    int k = threadIdx.x * 4;
    float4 x = make_float4(0.f, 0.f, 0.f, 0.f);
    if (m < TROWS) x = *(const float4*)(ttab + (size_t)m * DD + k);
    __nv_bfloat16 h0, l0, h1, l1, h2, l2, h3, l3;
    split32(x.x, h0, l0); split32(x.y, h1, l1);
    split32(x.z, h2, l2); split32(x.w, h3, l3);
    uint2 hw = make_uint2(packbf2(h0, h1), packbf2(h2, h3));
    uint2 lw = make_uint2(packbf2(l0, l1), packbf2(l2, l3));
    *(uint2*)(g_A1hi + (size_t)m * DD + k) = hw;
    *(uint2*)(g_A1lo + (size_t)m * DD + k) = lw;
}

// ---------------- prep: W[K,N] -> Wt[N,K] bf16 hi/lo (vectorized) ----------
__global__ void convW_kernel(const float* __restrict__ w1,
                             const float* __restrict__ w2)
{
    __shared__ float tile[32][33];
    int z = blockIdx.z;
    const float* W = z ? w2 : w1;
    __nv_bfloat16* Whi = z ? g_Wt2hi : g_Wt1hi;
    __nv_bfloat16* Wlo = z ? g_Wt2lo : g_Wt1lo;
    int n0 = blockIdx.x * 32, k0 = blockIdx.y * 32;
    int tid = threadIdx.x;      // 256 threads

    // coalesced load of 32x32 f32 tile (each thread one float4)
    int lr = tid >> 3, lc = (tid & 7) * 4;
    float4 v4 = *(const float4*)(W + (size_t)(k0 + lr) * DD + n0 + lc);
    tile[lr][lc] = v4.x; tile[lr][lc + 1] = v4.y;
    tile[lr][lc + 2] = v4.z; tile[lr][lc + 3] = v4.w;
    __syncthreads();

    // transposed write: each thread owns (n, 4 consecutive k) -> uint2 per table
    int n = tid >> 3, k4 = (tid & 7) * 4;
    float a = tile[k4][n], b = tile[k4 + 1][n];
    float c = tile[k4 + 2][n], d = tile[k4 + 3][n];
    __nv_bfloat16 ha, la, hb, lb, hc, lc2, hd, ld;
    split32(a, ha, la); split32(b, hb, lb);
    split32(c, hc, lc2); split32(d, hd, ld);
    size_t o = (size_t)(n0 + n) * DD + k0 + k4;
    *(uint2*)(Whi + o) = make_uint2(packbf2(ha, hb), packbf2(hc, hd));
    *(uint2*)(Wlo + o) = make_uint2(packbf2(la, lb), packbf2(lc2, ld));
}

// ---------------- mma.sync GEMM: C[1024,1024] = A @ W^T (+bias, opt SiLU) --
// CTA tile 128x64, K-chunk 32, double-buffered SMEM, 8 warps (4m x 2n),
// warp tile 32x32, ldmatrix fragments, 3 bf16 passes (hh + hl + lh) ~= fp32.
#define PITCH 80            // bytes per 32-col bf16 row (64B data + 16B pad)
#define ST_SZ 30720         // one stage: Ahi,Alo (10240 ea), Bhi,Blo (5120 ea)
__global__ void __launch_bounds__(256, 1)
gemm_mma_kernel(const float* __restrict__ bias, int stage)
{
    extern __shared__ __align__(16) char smem[];

    const __nv_bfloat16* Ahi = stage ? g_Ahhi : g_A1hi;
    const __nv_bfloat16* Alo = stage ? g_Ahlo : g_A1lo;
    const __nv_bfloat16* Bhi = stage ? g_Wt2hi : g_Wt1hi;
    const __nv_bfloat16* Blo = stage ? g_Wt2lo : g_Wt1lo;

    const int tid = threadIdx.x;
    const int lane = tid & 31;
    const int wid = tid >> 5;
    const int wm = wid & 3;           // 4 warps along M
    const int wn = wid >> 2;          // 2 warps along N
    const int m0 = blockIdx.y * 128;
    const int n0 = blockIdx.x * 64;

    const uint32_t sbase = (uint32_t)__cvta_generic_to_shared(smem);

    // ldmatrix lane address components
    const int laneA_row = lane & 15;
    const int laneA_k16 = ((lane >> 4) & 1) * 16;
    const int laneB_row = (lane & 7) | ((lane >> 1) & 8);
    const int laneB_k16 = (lane & 8) * 2;

    uint32_t offA[2], offB[2];
#pragma unroll
    for (int mf = 0; mf < 2; mf++)
        offA[mf] = (uint32_t)((wm * 32 + mf * 16 + laneA_row) * PITCH + laneA_k16);
#pragma unroll
    for (int p = 0; p < 2; p++)
        offB[p] = (uint32_t)(20480 + (wn * 32 + p * 16 + laneB_row) * PITCH + laneB_k16);

    float acc[2][4][4];
#pragma unroll
    for (int i = 0; i < 2; i++)
#pragma unroll
        for (int j = 0; j < 4; j++)
#pragma unroll
            for (int q = 0; q < 4; q++) acc[i][j][q] = 0.f;

#define LOAD_CHUNK(c_)                                                          \
    do {                                                                        \
        char* st = smem + ((c_) & 1) * ST_SZ;                                   \
        int k0 = (c_) * 32;                                                     \
        _Pragma("unroll")                                                       \
        for (int idx = tid; idx < 512; idx += 256) {                            \
            int r = idx >> 2, q = idx & 3;                                      \
            size_t g = (size_t)(m0 + r) * DD + k0 + q * 8;                      \
            *(uint4*)(st + r * PITCH + q * 16)         = *(const uint4*)(Ahi + g); \
            *(uint4*)(st + 10240 + r * PITCH + q * 16) = *(const uint4*)(Alo + g); \
        }                                                                       \
        {                                                                       \
            int r = tid >> 2, q = tid & 3;                                      \
            size_t g = (size_t)(n0 + r) * DD + k0 + q * 8;                      \
            *(uint4*)(st + 20480 + r * PITCH + q * 16) = *(const uint4*)(Bhi + g); \
            *(uint4*)(st + 25600 + r * PITCH + q * 16) = *(const uint4*)(Blo + g); \
        }                                                                       \
    } while (0)

    LOAD_CHUNK(0);
    __syncthreads();

    for (int c = 0; c < 32; c++) {
        if (c + 1 < 32) LOAD_CHUNK(c + 1);
        const uint32_t sst = sbase + (c & 1) * ST_SZ;

#pragma unroll
        for (int kk = 0; kk < 2; kk++) {
            const uint32_t kb = kk * 32;       // 16 bf16 = 32 bytes
            uint32_t ah[2][4], al[2][4], bh[2][4], bl[2][4];
#pragma unroll
            for (int mf = 0; mf < 2; mf++) {
                ldsm_x4(ah[mf], sst + offA[mf] + kb);
                ldsm_x4(al[mf], sst + 10240 + offA[mf] + kb);
            }
#pragma unroll
            for (int p = 0; p < 2; p++) {
                ldsm_x4_t(bh[p], sst + offB[p] + kb);
                ldsm_x4_t(bl[p], sst + 5120 + offB[p] + kb);
            }
#pragma unroll
            for (int mf = 0; mf < 2; mf++)
#pragma unroll
                for (int nf = 0; nf < 4; nf++) {
                    const int p = nf >> 1, ix = (nf & 1) * 2;
                    mma_bf16(acc[mf][nf], ah[mf], bh[p][ix], bh[p][ix + 1]);
                    mma_bf16(acc[mf][nf], ah[mf], bl[p][ix], bl[p][ix + 1]);
                    mma_bf16(acc[mf][nf], al[mf], bh[p][ix], bh[p][ix + 1]);
                }
        }
        __syncthreads();
    }

    // ---- epilogue: bias (+SiLU+split for stage 0) ----
#pragma unroll
    for (int mf = 0; mf < 2; mf++) {
#pragma unroll
        for (int nf = 0; nf < 4; nf++) {
            int col = n0 + wn * 32 + nf * 8 + (lane & 3) * 2;
            float2 bb = *(const float2*)(bias + col);
            int r0 = m0 + wm * 32 + mf * 16 + (lane >> 2);
#pragma unroll
            for (int half = 0; half < 2; half++) {
                int r = r0 + half * 8;
                float v0 = acc[mf][nf][2 * half + 0] + bb.x;
                float v1 = acc[mf][nf][2 * half + 1] + bb.y;
                if (stage == 0) {
                    v0 = __fdividef(v0, 1.0f + __expf(-v0));
                    v1 = __fdividef(v1, 1.0f + __expf(-v1));
                    __nv_bfloat16 h0, l0, h1, l1;
                    split32(v0, h0, l0);
                    split32(v1, h1, l1);
                    *(uint32_t*)(g_Ahhi + (size_t)r * DD + col) = packbf2(h0, h1);
                    *(uint32_t*)(g_Ahlo + (size_t)r * DD + col) = packbf2(l0, l1);
                } else {
                    *(float2*)(g_tmlp + (size_t)r * DD + col) = make_float2(v0, v1);
                }
            }
        }
    }
}

// ---------------- v[d] = sum_k pos_emb_w[k] * pos_feature_w[k,d] -----------
__global__ void v_kernel(const float* __restrict__ pew,
                         const float* __restrict__ pfw)
{
    int d = blockIdx.x * blockDim.x + threadIdx.x;
    if (d < DD) {
        float acc = 0.f;
#pragma unroll 8
        for (int k = 0; k < KK; k++)
            acc += pew[k] * pfw[k * DD + d];
        g_v[d] = acc;
    }
}

// ---------------- s[b,i] = softmax_j(SCALING/(r_ij+1)) . r_j (masked) ------
__global__ void s_kernel(const float* __restrict__ pos,
                         const int* __restrict__ token)
{
    __shared__ float px[LL], py[LL], pz[LL], rr[LL], mm[LL];
    int b = blockIdx.x >> 7;
    int q0 = (blockIdx.x & 127) * 8;
    int tid = threadIdx.x;

    for (int j = tid; j < LL; j += 256) {
        float x = pos[(size_t)(b * LL + j) * 3 + 0];
        float y = pos[(size_t)(b * LL + j) * 3 + 1];
        float z = pos[(size_t)(b * LL + j) * 3 + 2];
        px[j] = x; py[j] = y; pz[j] = z;
        float n2 = x * x + y * y + z * z;
        rr[j] = n2 * rsqrtf(fmaxf(n2, 1e-36f));
        mm[j] = (token[b * LL + j] != 0) ? 1.0f : 0.0f;
    }
    __syncthreads();

    int w = tid >> 5, lane = tid & 31;
    int q = q0 + w;
    float qx = px[q], qy = py[q], qz = pz[q];
    float se = 0.f, sr = 0.f;
#pragma unroll 4
    for (int j = lane; j < LL; j += 32) {
        float dx = px[j] - qx, dy = py[j] - qy, dz = pz[j] - qz;
        float n2 = dx * dx + dy * dy + dz * dz;
        float d = n2 * rsqrtf(fmaxf(n2, 1e-36f));
        float wt = __expf(__fdividef(SCALING, d + 1.0f)) * mm[j];
        se += wt;
        sr += wt * rr[j];
    }
#pragma unroll
    for (int o = 16; o > 0; o >>= 1) {
        se += __shfl_xor_sync(0xffffffffu, se, o);
        sr += __shfl_xor_sync(0xffffffffu, sr, o);
    }
    if (lane == 0)
        g_s[b * LL + q] = (mm[q] != 0.f) ? (sr / se) : 0.0f;
}

// ---------------- fused epilogue over [B,L,D] (+ padding mask tail) --------
__global__ void epilogue_kernel(const int* __restrict__ token,
                                const int* __restrict__ node_attr,
                                const int* __restrict__ ismol,
                                const int* __restrict__ tstep,
                                const float* __restrict__ embed,
                                const float* __restrict__ atab,
                                float* __restrict__ out,
                                int write_mask)
{
    __shared__ int sidx[8];
    __shared__ int stok, sts, smol;
    __shared__ float ss;
    int bl = blockIdx.x;
    int b = bl >> 10;
    int tid = threadIdx.x;
    if (tid < 8) sidx[tid] = node_attr[bl * 9 + 1 + tid];
    else if (tid == 8) stok = token[bl];
    else if (tid == 9) sts = tstep[bl];
    else if (tid == 10) smol = ismol[b];
    else if (tid == 11) ss = g_s[bl];
    __syncthreads();

    int d = tid * 4;
    float4 acc = *(const float4*)(embed + (size_t)stok * DD + d);
    float4 t4 = *(const float4*)(g_tmlp + (size_t)sts * DD + d);
    acc.x += t4.x; acc.y += t4.y; acc.z += t4.z; acc.w += t4.w;
    if (smol) {
#pragma unroll
        for (int j = 0; j < 8; j++) {
            float4 a4 = *(const float4*)(atab + (size_t)sidx[j] * DD + d);
            acc.x += a4.x; acc.y += a4.y; acc.z += a4.z; acc.w += a4.w;
        }
    }
    if (stok != 0) {
        float4 v4 = *(const float4*)(g_v + d);
        float s = ss;
        acc.x += s * v4.x; acc.y += s * v4.y; acc.z += s * v4.z; acc.w += s * v4.w;
    }
    *(float4*)(out + (size_t)bl * DD + d) = acc;

    if (write_mask && tid == 12)
        out[(size_t)BB * LL * DD + bl] = (stok == 0) ? 1.0f : 0.0f;
}

// ---------------------------------------------------------------------------
extern "C" void kernel_launch(void* const* d_in, const int* in_sizes, int n_in,
                              void* d_out, int out_size)
{
    const int*   token     = (const int*)d_in[0];
    const int*   node_attr = (const int*)d_in[1];
    const int*   ismol     = (const int*)d_in[2];
    const float* pos       = (const float*)d_in[3];
    const int*   tstep     = (const int*)d_in[4];
    const float* embed     = (const float*)d_in[5];
    const float* atab      = (const float*)d_in[6];
    const float* ttab      = (const float*)d_in[7];
    const float* w1        = (const float*)d_in[8];
    const float* b1        = (const float*)d_in[9];
    const float* w2        = (const float*)d_in[10];
    const float* b2        = (const float*)d_in[11];
    const float* pew       = (const float*)d_in[12];
    const float* pfw       = (const float*)d_in[13];
    float* out = (float*)d_out;

    const int DSMEM = 2 * ST_SZ;   // 61440 bytes
    cudaFuncSetAttribute(gemm_mma_kernel,
                         cudaFuncAttributeMaxDynamicSharedMemorySize, DSMEM);

    // independent small kernels
    v_kernel<<<(DD + 255) / 256, 256>>>(pew, pfw);
    s_kernel<<<BB * 128, 256>>>(pos, token);

    // bf16 hi/lo conversions
    convA_kernel<<<MPAD, 256>>>(ttab);
    convW_kernel<<<dim3(32, 32, 2), 256>>>(w1, w2);

    // time MLP via mma.sync bf16 hi/lo split (fp32 accumulate)
    gemm_mma_kernel<<<dim3(16, 8), 256, DSMEM>>>(b1, 0);
    gemm_mma_kernel<<<dim3(16, 8), 256, DSMEM>>>(b2, 1);

    // fused gather + add epilogue (+mask tail)
    int write_mask = (out_size >= BB * LL * DD + BB * LL) ? 1 : 0;
    epilogue_kernel<<<BB * LL, 256>>>(token, node_attr, ismol, tstep,
                                      embed, atab, out, write_mask);
}

// round 5
// speedup vs baseline: 3.8410x; 1.8493x over previous
#include <cuda_runtime.h>
#include <cuda_bf16.h>
#include <math.h>
#include <stdint.h>

// Problem constants
#define BB 8
#define LL 1024
#define DD 1024
#define KK 128
#define TROWS 1000
#define MPAD 1024
#define SCALING 0.08838834764831845f   // 128^-0.5

// ---------------- device scratch (no allocation allowed) -------------------
__device__ __align__(16) __nv_bfloat16 g_A1[MPAD * DD];   // bf16 time_table (padded)
__device__ __align__(16) __nv_bfloat16 g_Ah[MPAD * DD];   // bf16 silu(h)
__device__ __align__(16) __nv_bfloat16 g_W1[DD * DD];     // bf16 W1 [K][N] as-is
__device__ __align__(16) __nv_bfloat16 g_W2[DD * DD];     // bf16 W2 [K][N] as-is
__device__ __align__(16) float g_tmlp[MPAD * DD];
__device__ float g_v[DD];
__device__ float g_s[BB * LL];

// ---------------- small helpers --------------------------------------------
__device__ __forceinline__ uint32_t packbf2(__nv_bfloat16 a, __nv_bfloat16 b) {
    __nv_bfloat162 t; t.x = a; t.y = b;
    return *(uint32_t*)&t;
}
__device__ __forceinline__ void mma_bf16(float* c, const uint32_t* a,
                                         uint32_t b0, uint32_t b1) {
    asm volatile(
        "mma.sync.aligned.m16n8k16.row.col.f32.bf16.bf16.f32 "
        "{%0,%1,%2,%3}, {%4,%5,%6,%7}, {%8,%9}, {%0,%1,%2,%3};"
        : "+f"(c[0]), "+f"(c[1]), "+f"(c[2]), "+f"(c[3])
        : "r"(a[0]), "r"(a[1]), "r"(a[2]), "r"(a[3]), "r"(b0), "r"(b1));
}
__device__ __forceinline__ void ldsm_x4(uint32_t* r, uint32_t addr) {
    asm volatile("ldmatrix.sync.aligned.m8n8.x4.shared.b16 {%0,%1,%2,%3}, [%4];"
                 : "=r"(r[0]), "=r"(r[1]), "=r"(r[2]), "=r"(r[3]) : "r"(addr));
}
__device__ __forceinline__ void ldsm_x4_t(uint32_t* r, uint32_t addr) {
    asm volatile("ldmatrix.sync.aligned.m8n8.x4.trans.shared.b16 {%0,%1,%2,%3}, [%4];"
                 : "=r"(r[0]), "=r"(r[1]), "=r"(r[2]), "=r"(r[3]) : "r"(addr));
}
#define CP16(dst, src) \
    asm volatile("cp.async.cg.shared.global [%0], [%1], 16;" \
                 :: "r"(dst), "l"(src) : "memory")
#define CP_COMMIT() asm volatile("cp.async.commit_group;" ::: "memory")
#define CP_WAIT2()  asm volatile("cp.async.wait_group 2;" ::: "memory")

// ---------------- prep: time_table -> bf16 (pad to 1024 rows) --------------
__global__ void convA_kernel(const float* __restrict__ ttab)
{
    int m = blockIdx.x;
    int k = threadIdx.x * 4;
    float4 x = make_float4(0.f, 0.f, 0.f, 0.f);
    if (m < TROWS) x = *(const float4*)(ttab + (size_t)m * DD + k);
    *(uint2*)(g_A1 + (size_t)m * DD + k) =
        make_uint2(packbf2(__float2bfloat16(x.x), __float2bfloat16(x.y)),
                   packbf2(__float2bfloat16(x.z), __float2bfloat16(x.w)));
}

// ---------------- prep: W f32 -> bf16 cast (NO transpose; [K][N] kept) -----
__global__ void convW_kernel(const float* __restrict__ w1,
                             const float* __restrict__ w2)
{
    int i = blockIdx.x * blockDim.x + threadIdx.x;     // 0..524287
    const float* W = (i < 262144) ? w1 : w2;
    __nv_bfloat16* O = (i < 262144) ? g_W1 : g_W2;
    int j = (i & 262143) * 4;
    float4 v = *(const float4*)(W + j);
    *(uint2*)(O + j) =
        make_uint2(packbf2(__float2bfloat16(v.x), __float2bfloat16(v.y)),
                   packbf2(__float2bfloat16(v.z), __float2bfloat16(v.w)));
}

// ---------------- bf16 GEMM: C[1024,1024] = A[M,K] @ W[K,N] (+bias,opt SiLU)
// CTA tile 128x64, K-chunk 32, 4-stage cp.async pipeline, 8 warps (4m x 2n).
// A: [m][k] row-major bf16 smem, pitch 80 (conflict-free ldmatrix)
// B: W [k][n] row-major bf16 smem, pitch 144 (conflict-free ldmatrix.trans)
#define PITCH_A 80
#define PITCH_B 144
#define OFF_B 10240
#define STG 14848
__global__ void __launch_bounds__(256, 1)
gemm_mma_kernel(const float* __restrict__ bias, int stage)
{
    extern __shared__ __align__(16) char smem[];

    const __nv_bfloat16* A = stage ? g_Ah : g_A1;
    const __nv_bfloat16* W = stage ? g_W2 : g_W1;

    const int tid = threadIdx.x;
    const int lane = tid & 31;
    const int wid = tid >> 5;
    const int wm = wid & 3;           // 4 warps along M
    const int wn = wid >> 2;          // 2 warps along N
    const int m0 = blockIdx.y * 128;
    const int n0 = blockIdx.x * 64;

    const uint32_t sbase = (uint32_t)__cvta_generic_to_shared(smem);

    // cp.async per-thread slots
    const int ar = tid >> 2;              // A rows (0..63, +64)
    const int aqB = (tid & 3) * 16;       // byte col within 64B row
    const int br = tid >> 3;              // B row (k, 0..31)
    const int bqB = (tid & 7) * 16;       // byte col within 128B row

    // ldmatrix fragment offsets
    uint32_t offA[2];
#pragma unroll
    for (int mf = 0; mf < 2; mf++)
        offA[mf] = (uint32_t)((wm * 32 + mf * 16 + (lane & 15)) * PITCH_A
                              + ((lane >> 4) & 1) * 16);
    const uint32_t offB = (uint32_t)(OFF_B + (lane & 15) * PITCH_B
                                     + (wn * 32 + ((lane >> 4) & 1) * 8) * 2);

    float acc[2][4][4];
#pragma unroll
    for (int i = 0; i < 2; i++)
#pragma unroll
        for (int j = 0; j < 4; j++)
#pragma unroll
            for (int q = 0; q < 4; q++) acc[i][j][q] = 0.f;

#define ISSUE(c_)                                                               \
    do {                                                                        \
        uint32_t st = sbase + ((c_) & 3) * STG;                                 \
        int k0 = (c_) * 32;                                                     \
        CP16(st + ar * PITCH_A + aqB,                                           \
             A + (size_t)(m0 + ar) * DD + k0 + (aqB >> 1));                     \
        CP16(st + (ar + 64) * PITCH_A + aqB,                                    \
             A + (size_t)(m0 + ar + 64) * DD + k0 + (aqB >> 1));                \
        CP16(st + OFF_B + br * PITCH_B + bqB,                                   \
             W + (size_t)(k0 + br) * DD + n0 + (bqB >> 1));                     \
    } while (0)

    ISSUE(0); CP_COMMIT();
    ISSUE(1); CP_COMMIT();
    ISSUE(2); CP_COMMIT();

    for (int c = 0; c < 32; c++) {
        CP_WAIT2();
        __syncthreads();
        const uint32_t sst = sbase + (c & 3) * STG;

#pragma unroll
        for (int kk = 0; kk < 2; kk++) {
            uint32_t ah[2][4], bf[2][4];
#pragma unroll
            for (int mf = 0; mf < 2; mf++)
                ldsm_x4(ah[mf], sst + offA[mf] + kk * 32);
#pragma unroll
            for (int p = 0; p < 2; p++)
                ldsm_x4_t(bf[p], sst + offB + kk * 16 * PITCH_B + p * 32);
#pragma unroll
            for (int mf = 0; mf < 2; mf++)
#pragma unroll
                for (int nf = 0; nf < 4; nf++) {
                    const int p = nf >> 1, ix = (nf & 1) * 2;
                    mma_bf16(acc[mf][nf], ah[mf], bf[p][ix], bf[p][ix + 1]);
                }
        }
        if (c + 3 < 32) ISSUE(c + 3);
        CP_COMMIT();
    }

    // ---- epilogue: bias (+SiLU for stage 0) ----
#pragma unroll
    for (int mf = 0; mf < 2; mf++) {
#pragma unroll
        for (int nf = 0; nf < 4; nf++) {
            int col = n0 + wn * 32 + nf * 8 + (lane & 3) * 2;
            float2 bb = *(const float2*)(bias + col);
            int r0 = m0 + wm * 32 + mf * 16 + (lane >> 2);
#pragma unroll
            for (int half = 0; half < 2; half++) {
                int r = r0 + half * 8;
                float v0 = acc[mf][nf][2 * half + 0] + bb.x;
                float v1 = acc[mf][nf][2 * half + 1] + bb.y;
                if (stage == 0) {
                    v0 = __fdividef(v0, 1.0f + __expf(-v0));
                    v1 = __fdividef(v1, 1.0f + __expf(-v1));
                    *(uint32_t*)(g_Ah + (size_t)r * DD + col) =
                        packbf2(__float2bfloat16(v0), __float2bfloat16(v1));
                } else {
                    *(float2*)(g_tmlp + (size_t)r * DD + col) = make_float2(v0, v1);
                }
            }
        }
    }
}

// ---------------- v[d] = sum_k pos_emb_w[k] * pos_feature_w[k,d] -----------
__global__ void v_kernel(const float* __restrict__ pew,
                         const float* __restrict__ pfw)
{
    int d = blockIdx.x * blockDim.x + threadIdx.x;
    if (d < DD) {
        float acc = 0.f;
#pragma unroll 8
        for (int k = 0; k < KK; k++)
            acc += pew[k] * pfw[k * DD + d];
        g_v[d] = acc;
    }
}

// ---------------- s[b,i] = softmax_j(SCALING/(r_ij+1)) . r_j (masked) ------
__global__ void s_kernel(const float* __restrict__ pos,
                         const int* __restrict__ token)
{
    __shared__ float px[LL], py[LL], pz[LL], rr[LL], mm[LL];
    int b = blockIdx.x >> 7;
    int q0 = (blockIdx.x & 127) * 8;
    int tid = threadIdx.x;

    for (int j = tid; j < LL; j += 256) {
        float x = pos[(size_t)(b * LL + j) * 3 + 0];
        float y = pos[(size_t)(b * LL + j) * 3 + 1];
        float z = pos[(size_t)(b * LL + j) * 3 + 2];
        px[j] = x; py[j] = y; pz[j] = z;
        float n2 = x * x + y * y + z * z;
        rr[j] = n2 * rsqrtf(fmaxf(n2, 1e-36f));
        mm[j] = (token[b * LL + j] != 0) ? 1.0f : 0.0f;
    }
    __syncthreads();

    int w = tid >> 5, lane = tid & 31;
    int q = q0 + w;
    float qx = px[q], qy = py[q], qz = pz[q];
    float se = 0.f, sr = 0.f;
#pragma unroll 4
    for (int j = lane; j < LL; j += 32) {
        float dx = px[j] - qx, dy = py[j] - qy, dz = pz[j] - qz;
        float n2 = dx * dx + dy * dy + dz * dz;
        float d = n2 * rsqrtf(fmaxf(n2, 1e-36f));
        float wt = __expf(__fdividef(SCALING, d + 1.0f)) * mm[j];
        se += wt;
        sr += wt * rr[j];
    }
#pragma unroll
    for (int o = 16; o > 0; o >>= 1) {
        se += __shfl_xor_sync(0xffffffffu, se, o);
        sr += __shfl_xor_sync(0xffffffffu, sr, o);
    }
    if (lane == 0)
        g_s[b * LL + q] = (mm[q] != 0.f) ? (sr / se) : 0.0f;
}

// ---------------- fused epilogue over [B,L,D] (+ padding mask tail) --------
__global__ void epilogue_kernel(const int* __restrict__ token,
                                const int* __restrict__ node_attr,
                                const int* __restrict__ ismol,
                                const int* __restrict__ tstep,
                                const float* __restrict__ embed,
                                const float* __restrict__ atab,
                                float* __restrict__ out,
                                int write_mask)
{
    __shared__ int sidx[8];
    __shared__ int stok, sts, smol;
    __shared__ float ss;
    int bl = blockIdx.x;
    int b = bl >> 10;
    int tid = threadIdx.x;
    if (tid < 8) sidx[tid] = node_attr[bl * 9 + 1 + tid];
    else if (tid == 8) stok = token[bl];
    else if (tid == 9) sts = tstep[bl];
    else if (tid == 10) smol = ismol[b];
    else if (tid == 11) ss = g_s[bl];
    __syncthreads();

    int d = tid * 4;
    float4 acc = *(const float4*)(embed + (size_t)stok * DD + d);
    float4 t4 = *(const float4*)(g_tmlp + (size_t)sts * DD + d);
    acc.x += t4.x; acc.y += t4.y; acc.z += t4.z; acc.w += t4.w;
    if (smol) {
#pragma unroll
        for (int j = 0; j < 8; j++) {
            float4 a4 = *(const float4*)(atab + (size_t)sidx[j] * DD + d);
            acc.x += a4.x; acc.y += a4.y; acc.z += a4.z; acc.w += a4.w;
        }
    }
    if (stok != 0) {
        float4 v4 = *(const float4*)(g_v + d);
        float s = ss;
        acc.x += s * v4.x; acc.y += s * v4.y; acc.z += s * v4.z; acc.w += s * v4.w;
    }
    *(float4*)(out + (size_t)bl * DD + d) = acc;

    if (write_mask && tid == 12)
        out[(size_t)BB * LL * DD + bl] = (stok == 0) ? 1.0f : 0.0f;
}

// ---------------------------------------------------------------------------
extern "C" void kernel_launch(void* const* d_in, const int* in_sizes, int n_in,
                              void* d_out, int out_size)
{
    const int*   token     = (const int*)d_in[0];
    const int*   node_attr = (const int*)d_in[1];
    const int*   ismol     = (const int*)d_in[2];
    const float* pos       = (const float*)d_in[3];
    const int*   tstep     = (const int*)d_in[4];
    const float* embed     = (const float*)d_in[5];
    const float* atab      = (const float*)d_in[6];
    const float* ttab      = (const float*)d_in[7];
    const float* w1        = (const float*)d_in[8];
    const float* b1        = (const float*)d_in[9];
    const float* w2        = (const float*)d_in[10];
    const float* b2        = (const float*)d_in[11];
    const float* pew       = (const float*)d_in[12];
    const float* pfw       = (const float*)d_in[13];
    float* out = (float*)d_out;

    const int DSMEM = 4 * STG;   // 59392 bytes
    cudaFuncSetAttribute(gemm_mma_kernel,
                         cudaFuncAttributeMaxDynamicSharedMemorySize, DSMEM);

    // independent small kernels
    v_kernel<<<(DD + 255) / 256, 256>>>(pew, pfw);
    s_kernel<<<BB * 128, 256>>>(pos, token);

    // bf16 casts (no transpose needed anymore)
    convA_kernel<<<MPAD, 256>>>(ttab);
    convW_kernel<<<2048, 256>>>(w1, w2);

    // time MLP via mma.sync bf16 (fp32 accumulate)
    gemm_mma_kernel<<<dim3(16, 8), 256, DSMEM>>>(b1, 0);
    gemm_mma_kernel<<<dim3(16, 8), 256, DSMEM>>>(b2, 1);

    // fused gather + add epilogue (+mask tail)
    int write_mask = (out_size >= BB * LL * DD + BB * LL) ? 1 : 0;
    epilogue_kernel<<<BB * LL, 256>>>(token, node_attr, ismol, tstep,
                                      embed, atab, out, write_mask);
}

// round 6
// speedup vs baseline: 4.0504x; 1.0545x over previous
#include <cuda_runtime.h>
#include <cuda_bf16.h>
#include <math.h>
#include <stdint.h>

// Problem constants
#define BB 8
#define LL 1024
#define DD 1024
#define KK 128
#define TROWS 1000
#define MPAD 1024
#define SCALING 0.08838834764831845f   // 128^-0.5

// ---------------- device scratch (no allocation allowed) -------------------
__device__ __align__(16) __nv_bfloat16 g_A1[MPAD * DD];    // bf16 time_table
__device__ __align__(16) __nv_bfloat16 g_Ah[MPAD * DD];    // bf16 silu(h)
__device__ __align__(16) __nv_bfloat16 g_W1[DD * DD];      // bf16 W1 [K][N]
__device__ __align__(16) __nv_bfloat16 g_W2[DD * DD];      // bf16 W2 [K][N]
__device__ __align__(16) __nv_bfloat16 g_tmlpb[MPAD * DD]; // bf16 mlp out
__device__ __align__(16) __nv_bfloat16 g_embb[160 * DD];   // bf16 embed table
__device__ __align__(16) __nv_bfloat16 g_atb[512 * DD];    // bf16 atom table
__device__ float g_v[DD];
__device__ float g_s[BB * LL];

// ---------------- small helpers --------------------------------------------
__device__ __forceinline__ uint32_t packbf2(float a, float b) {
    __nv_bfloat162 t;
    t.x = __float2bfloat16(a);
    t.y = __float2bfloat16(b);
    return *(uint32_t*)&t;
}
__device__ __forceinline__ float4 bfq(uint2 u) {
    __nv_bfloat162 a = *(__nv_bfloat162*)&u.x;
    __nv_bfloat162 b = *(__nv_bfloat162*)&u.y;
    return make_float4(__bfloat162float(a.x), __bfloat162float(a.y),
                       __bfloat162float(b.x), __bfloat162float(b.y));
}
__device__ __forceinline__ void mma_bf16(float* c, const uint32_t* a,
                                         uint32_t b0, uint32_t b1) {
    asm volatile(
        "mma.sync.aligned.m16n8k16.row.col.f32.bf16.bf16.f32 "
        "{%0,%1,%2,%3}, {%4,%5,%6,%7}, {%8,%9}, {%0,%1,%2,%3};"
        : "+f"(c[0]), "+f"(c[1]), "+f"(c[2]), "+f"(c[3])
        : "r"(a[0]), "r"(a[1]), "r"(a[2]), "r"(a[3]), "r"(b0), "r"(b1));
}
__device__ __forceinline__ void ldsm_x4(uint32_t* r, uint32_t addr) {
    asm volatile("ldmatrix.sync.aligned.m8n8.x4.shared.b16 {%0,%1,%2,%3}, [%4];"
                 : "=r"(r[0]), "=r"(r[1]), "=r"(r[2]), "=r"(r[3]) : "r"(addr));
}
__device__ __forceinline__ void ldsm_x4_t(uint32_t* r, uint32_t addr) {
    asm volatile("ldmatrix.sync.aligned.m8n8.x4.trans.shared.b16 {%0,%1,%2,%3}, [%4];"
                 : "=r"(r[0]), "=r"(r[1]), "=r"(r[2]), "=r"(r[3]) : "r"(addr));
}
#define CP16(dst, src) \
    asm volatile("cp.async.cg.shared.global [%0], [%1], 16;" \
                 :: "r"(dst), "l"(src) : "memory")
#define CP_COMMIT() asm volatile("cp.async.commit_group;" ::: "memory")
#define CP_WAIT2()  asm volatile("cp.async.wait_group 2;" ::: "memory")

// ---------------- fused prep: all f32->bf16 casts + v vector ---------------
// float4 segments: [0,262144) ttab->g_A1 (zero-pad m>=1000)
//                  [262144,524288) w1, [524288,786432) w2,
//                  [786432,827392) embed, [827392,958464) atab
// blocks [3744,3748): v[d] = pos_emb_w . pos_feature_w[:,d]
__global__ void prep_kernel(const float* __restrict__ ttab,
                            const float* __restrict__ w1,
                            const float* __restrict__ w2,
                            const float* __restrict__ embed,
                            const float* __restrict__ atab,
                            const float* __restrict__ pew,
                            const float* __restrict__ pfw)
{
    if (blockIdx.x >= 3744) {
        int d = (blockIdx.x - 3744) * 256 + threadIdx.x;
        float acc = 0.f;
#pragma unroll 8
        for (int k = 0; k < KK; k++)
            acc += pew[k] * pfw[k * DD + d];
        g_v[d] = acc;
        return;
    }
    int i = blockIdx.x * 256 + threadIdx.x;   // float4 index
    const float4* src;
    __nv_bfloat16* dst;
    int off;
    float4 v;
    if (i < 262144) {
        int m = i >> 8;
        v = (m < TROWS) ? ((const float4*)ttab)[i] : make_float4(0.f, 0.f, 0.f, 0.f);
        dst = g_A1; off = i;
        *(uint2*)(dst + off * 4) = make_uint2(packbf2(v.x, v.y), packbf2(v.z, v.w));
        return;
    } else if (i < 524288) { src = (const float4*)w1;    dst = g_W1;  off = i - 262144; }
    else if (i < 786432)   { src = (const float4*)w2;    dst = g_W2;  off = i - 524288; }
    else if (i < 827392)   { src = (const float4*)embed; dst = g_embb; off = i - 786432; }
    else                   { src = (const float4*)atab;  dst = g_atb;  off = i - 827392; }
    v = src[off];
    *(uint2*)(dst + off * 4) = make_uint2(packbf2(v.x, v.y), packbf2(v.z, v.w));
}

// ---------------- bf16 GEMM: C[1024,1024] = A[M,K] @ W[K,N] (+bias,opt SiLU)
// CTA tile 128x64, K-chunk 32, 4-stage cp.async pipeline, 8 warps (4m x 2n).
#define PITCH_A 80
#define PITCH_B 144
#define OFF_B 10240
#define STG 14848
__global__ void __launch_bounds__(256, 1)
gemm_mma_kernel(const float* __restrict__ bias, int stage)
{
    extern __shared__ __align__(16) char smem[];

    const __nv_bfloat16* A = stage ? g_Ah : g_A1;
    const __nv_bfloat16* W = stage ? g_W2 : g_W1;

    const int tid = threadIdx.x;
    const int lane = tid & 31;
    const int wid = tid >> 5;
    const int wm = wid & 3;
    const int wn = wid >> 2;
    const int m0 = blockIdx.y * 128;
    const int n0 = blockIdx.x * 64;

    const uint32_t sbase = (uint32_t)__cvta_generic_to_shared(smem);

    const int ar = tid >> 2;
    const int aqB = (tid & 3) * 16;
    const int br = tid >> 3;
    const int bqB = (tid & 7) * 16;

    uint32_t offA[2];
#pragma unroll
    for (int mf = 0; mf < 2; mf++)
        offA[mf] = (uint32_t)((wm * 32 + mf * 16 + (lane & 15)) * PITCH_A
                              + ((lane >> 4) & 1) * 16);
    const uint32_t offB = (uint32_t)(OFF_B + (lane & 15) * PITCH_B
                                     + (wn * 32 + ((lane >> 4) & 1) * 8) * 2);

    float acc[2][4][4];
#pragma unroll
    for (int i = 0; i < 2; i++)
#pragma unroll
        for (int j = 0; j < 4; j++)
#pragma unroll
            for (int q = 0; q < 4; q++) acc[i][j][q] = 0.f;

#define ISSUE(c_)                                                               \
    do {                                                                        \
        uint32_t st = sbase + ((c_) & 3) * STG;                                 \
        int k0 = (c_) * 32;                                                     \
        CP16(st + ar * PITCH_A + aqB,                                           \
             A + (size_t)(m0 + ar) * DD + k0 + (aqB >> 1));                     \
        CP16(st + (ar + 64) * PITCH_A + aqB,                                    \
             A + (size_t)(m0 + ar + 64) * DD + k0 + (aqB >> 1));                \
        CP16(st + OFF_B + br * PITCH_B + bqB,                                   \
             W + (size_t)(k0 + br) * DD + n0 + (bqB >> 1));                     \
    } while (0)

    ISSUE(0); CP_COMMIT();
    ISSUE(1); CP_COMMIT();
    ISSUE(2); CP_COMMIT();

    for (int c = 0; c < 32; c++) {
        CP_WAIT2();
        __syncthreads();
        const uint32_t sst = sbase + (c & 3) * STG;

#pragma unroll
        for (int kk = 0; kk < 2; kk++) {
            uint32_t ah[2][4], bf[2][4];
#pragma unroll
            for (int mf = 0; mf < 2; mf++)
                ldsm_x4(ah[mf], sst + offA[mf] + kk * 32);
#pragma unroll
            for (int p = 0; p < 2; p++)
                ldsm_x4_t(bf[p], sst + offB + kk * 16 * PITCH_B + p * 32);
#pragma unroll
            for (int mf = 0; mf < 2; mf++)
#pragma unroll
                for (int nf = 0; nf < 4; nf++) {
                    const int p = nf >> 1, ix = (nf & 1) * 2;
                    mma_bf16(acc[mf][nf], ah[mf], bf[p][ix], bf[p][ix + 1]);
                }
        }
        if (c + 3 < 32) ISSUE(c + 3);
        CP_COMMIT();
    }

    // ---- epilogue: bias (+SiLU for stage 0); bf16 outputs both stages ----
#pragma unroll
    for (int mf = 0; mf < 2; mf++) {
#pragma unroll
        for (int nf = 0; nf < 4; nf++) {
            int col = n0 + wn * 32 + nf * 8 + (lane & 3) * 2;
            float2 bb = *(const float2*)(bias + col);
            int r0 = m0 + wm * 32 + mf * 16 + (lane >> 2);
#pragma unroll
            for (int half = 0; half < 2; half++) {
                int r = r0 + half * 8;
                float v0 = acc[mf][nf][2 * half + 0] + bb.x;
                float v1 = acc[mf][nf][2 * half + 1] + bb.y;
                if (stage == 0) {
                    v0 = __fdividef(v0, 1.0f + __expf(-v0));
                    v1 = __fdividef(v1, 1.0f + __expf(-v1));
                    *(uint32_t*)(g_Ah + (size_t)r * DD + col) = packbf2(v0, v1);
                } else {
                    *(uint32_t*)(g_tmlpb + (size_t)r * DD + col) = packbf2(v0, v1);
                }
            }
        }
    }
}

// ---------------- s[b,i] = softmax_j(SCALING/(r_ij+1)) . r_j (masked) ------
// keys in registers, 8 register-resident queries per block, poly-exp.
__global__ void s_kernel(const float* __restrict__ pos,
                         const int* __restrict__ token)
{
    __shared__ float px[LL], py[LL], pz[LL], rr[LL], mm[LL];
    __shared__ float red[8][8][2];
    int b = blockIdx.x >> 7;
    int q0 = (blockIdx.x & 127) * 8;
    int tid = threadIdx.x;
    int w = tid >> 5, lane = tid & 31;

    for (int j = tid; j < LL; j += 256) {
        float x = pos[(size_t)(b * LL + j) * 3 + 0];
        float y = pos[(size_t)(b * LL + j) * 3 + 1];
        float z = pos[(size_t)(b * LL + j) * 3 + 2];
        px[j] = x; py[j] = y; pz[j] = z;
        float n2 = x * x + y * y + z * z;
        rr[j] = n2 * rsqrtf(fmaxf(n2, 1e-36f));
        mm[j] = (token[b * LL + j] != 0) ? 1.0f : 0.0f;
    }
    __syncthreads();

    float qx[8], qy[8], qz[8];
#pragma unroll
    for (int qq = 0; qq < 8; qq++) {
        qx[qq] = px[q0 + qq]; qy[qq] = py[q0 + qq]; qz[qq] = pz[q0 + qq];
    }
    float se[8], sr[8];
#pragma unroll
    for (int qq = 0; qq < 8; qq++) { se[qq] = 0.f; sr[qq] = 0.f; }

#pragma unroll
    for (int ch = 0; ch < 4; ch++) {
        int j = ch * 256 + w * 32 + lane;
        float kx = px[j], ky = py[j], kz = pz[j];
        float kr = rr[j], km = mm[j];
#pragma unroll
        for (int qq = 0; qq < 8; qq++) {
            float dx = kx - qx[qq], dy = ky - qy[qq], dz = kz - qz[qq];
            float n2 = dx * dx + dy * dy + dz * dz;
            float d = n2 * rsqrtf(fmaxf(n2, 1e-36f));
            float x = __fdividef(SCALING, d + 1.0f);
            // exp(x), x in (0, 0.0884]: 4th-order Taylor (abs err ~4e-9)
            float p = fmaf(x, 0.041666667f, 0.16666667f);
            p = fmaf(x, p, 0.5f);
            p = fmaf(x, p, 1.0f);
            float e = fmaf(x, p, 1.0f);
            float wt = e * km;
            se[qq] += wt;
            sr[qq] = fmaf(wt, kr, sr[qq]);
        }
    }

#pragma unroll
    for (int qq = 0; qq < 8; qq++) {
        float a = se[qq], c = sr[qq];
#pragma unroll
        for (int o = 16; o > 0; o >>= 1) {
            a += __shfl_xor_sync(0xffffffffu, a, o);
            c += __shfl_xor_sync(0xffffffffu, c, o);
        }
        if (lane == 0) { red[w][qq][0] = a; red[w][qq][1] = c; }
    }
    __syncthreads();
    if (tid < 8) {
        float SE = 0.f, SR = 0.f;
#pragma unroll
        for (int ww = 0; ww < 8; ww++) { SE += red[ww][tid][0]; SR += red[ww][tid][1]; }
        g_s[b * LL + q0 + tid] = (mm[q0 + tid] != 0.f) ? (SR / SE) : 0.0f;
    }
}

// ---------------- fused epilogue over [B,L,D] (+ padding mask tail) --------
__global__ void epilogue_kernel(const int* __restrict__ token,
                                const int* __restrict__ node_attr,
                                const int* __restrict__ ismol,
                                const int* __restrict__ tstep,
                                float* __restrict__ out,
                                int write_mask)
{
    __shared__ int sidx[8];
    __shared__ int stok, sts, smol;
    __shared__ float ss;
    int bl = blockIdx.x;
    int b = bl >> 10;
    int tid = threadIdx.x;
    if (tid < 8) sidx[tid] = node_attr[bl * 9 + 1 + tid];
    else if (tid == 8) stok = token[bl];
    else if (tid == 9) sts = tstep[bl];
    else if (tid == 10) smol = ismol[b];
    else if (tid == 11) ss = g_s[bl];
    __syncthreads();

    int d = tid * 4;
    float4 acc = bfq(*(const uint2*)(g_embb + (size_t)stok * DD + d));
    float4 t4 = bfq(*(const uint2*)(g_tmlpb + (size_t)sts * DD + d));
    acc.x += t4.x; acc.y += t4.y; acc.z += t4.z; acc.w += t4.w;
    if (smol) {
#pragma unroll
        for (int j = 0; j < 8; j++) {
            float4 a4 = bfq(*(const uint2*)(g_atb + (size_t)sidx[j] * DD + d));
            acc.x += a4.x; acc.y += a4.y; acc.z += a4.z; acc.w += a4.w;
        }
    }
    if (stok != 0) {
        float4 v4 = *(const float4*)(g_v + d);
        float s = ss;
        acc.x += s * v4.x; acc.y += s * v4.y; acc.z += s * v4.z; acc.w += s * v4.w;
    }
    *(float4*)(out + (size_t)bl * DD + d) = acc;

    if (write_mask && tid == 12)
        out[(size_t)BB * LL * DD + bl] = (stok == 0) ? 1.0f : 0.0f;
}

// ---------------------------------------------------------------------------
extern "C" void kernel_launch(void* const* d_in, const int* in_sizes, int n_in,
                              void* d_out, int out_size)
{
    const int*   token     = (const int*)d_in[0];
    const int*   node_attr = (const int*)d_in[1];
    const int*   ismol     = (const int*)d_in[2];
    const float* pos       = (const float*)d_in[3];
    const int*   tstep     = (const int*)d_in[4];
    const float* embed     = (const float*)d_in[5];
    const float* atab      = (const float*)d_in[6];
    const float* ttab      = (const float*)d_in[7];
    const float* w1        = (const float*)d_in[8];
    const float* b1        = (const float*)d_in[9];
    const float* w2        = (const float*)d_in[10];
    const float* b2        = (const float*)d_in[11];
    const float* pew       = (const float*)d_in[12];
    const float* pfw       = (const float*)d_in[13];
    float* out = (float*)d_out;

    const int DSMEM = 4 * STG;   // 59392 bytes
    cudaFuncSetAttribute(gemm_mma_kernel,
                         cudaFuncAttributeMaxDynamicSharedMemorySize, DSMEM);

    // fused prep (all bf16 casts + v) and s scalar
    prep_kernel<<<3748, 256>>>(ttab, w1, w2, embed, atab, pew, pfw);
    s_kernel<<<BB * 128, 256>>>(pos, token);

    // time MLP via mma.sync bf16 (fp32 accumulate)
    gemm_mma_kernel<<<dim3(16, 8), 256, DSMEM>>>(b1, 0);
    gemm_mma_kernel<<<dim3(16, 8), 256, DSMEM>>>(b2, 1);

    // fused gather + add epilogue (+mask tail)
    int write_mask = (out_size >= BB * LL * DD + BB * LL) ? 1 : 0;
    epilogue_kernel<<<BB * LL, 256>>>(token, node_attr, ismol, tstep,
                                      out, write_mask);
}

// round 7
// speedup vs baseline: 4.3551x; 1.0752x over previous
#include <cuda_runtime.h>
#include <cuda_bf16.h>
#include <math.h>
#include <stdint.h>

// Problem constants
#define BB 8
#define LL 1024
#define DD 1024
#define KK 128
#define TROWS 1000
#define MPAD 1024
#define SCALING 0.08838834764831845f   // 128^-0.5

// ---------------- device scratch (no allocation allowed) -------------------
__device__ __align__(16) __nv_bfloat16 g_A1[MPAD * DD];    // bf16 time_table
__device__ __align__(16) __nv_bfloat16 g_Ah[MPAD * DD];    // bf16 silu(h)
__device__ __align__(16) __nv_bfloat16 g_W1[DD * DD];      // bf16 W1 [K][N]
__device__ __align__(16) __nv_bfloat16 g_W2[DD * DD];      // bf16 W2 [K][N]
__device__ __align__(16) __nv_bfloat16 g_tmlpb[MPAD * DD]; // bf16 mlp out
__device__ __align__(16) __nv_bfloat16 g_embb[160 * DD];   // bf16 embed table
__device__ __align__(16) __nv_bfloat16 g_atb[512 * DD];    // bf16 atom table
__device__ float g_v[DD];
__device__ float g_s[BB * LL];

// ---------------- small helpers --------------------------------------------
__device__ __forceinline__ uint32_t packbf2(float a, float b) {
    __nv_bfloat162 t;
    t.x = __float2bfloat16(a);
    t.y = __float2bfloat16(b);
    return *(uint32_t*)&t;
}
__device__ __forceinline__ float4 bfq(uint2 u) {
    __nv_bfloat162 a = *(__nv_bfloat162*)&u.x;
    __nv_bfloat162 b = *(__nv_bfloat162*)&u.y;
    return make_float4(__bfloat162float(a.x), __bfloat162float(a.y),
                       __bfloat162float(b.x), __bfloat162float(b.y));
}
__device__ __forceinline__ void mma_bf16(float* c, const uint32_t* a,
                                         uint32_t b0, uint32_t b1) {
    asm volatile(
        "mma.sync.aligned.m16n8k16.row.col.f32.bf16.bf16.f32 "
        "{%0,%1,%2,%3}, {%4,%5,%6,%7}, {%8,%9}, {%0,%1,%2,%3};"
        : "+f"(c[0]), "+f"(c[1]), "+f"(c[2]), "+f"(c[3])
        : "r"(a[0]), "r"(a[1]), "r"(a[2]), "r"(a[3]), "r"(b0), "r"(b1));
}
__device__ __forceinline__ void ldsm_x4(uint32_t* r, uint32_t addr) {
    asm volatile("ldmatrix.sync.aligned.m8n8.x4.shared.b16 {%0,%1,%2,%3}, [%4];"
                 : "=r"(r[0]), "=r"(r[1]), "=r"(r[2]), "=r"(r[3]) : "r"(addr));
}
__device__ __forceinline__ void ldsm_x4_t(uint32_t* r, uint32_t addr) {
    asm volatile("ldmatrix.sync.aligned.m8n8.x4.trans.shared.b16 {%0,%1,%2,%3}, [%4];"
                 : "=r"(r[0]), "=r"(r[1]), "=r"(r[2]), "=r"(r[3]) : "r"(addr));
}
#define CP16(dst, src) \
    asm volatile("cp.async.cg.shared.global [%0], [%1], 16;" \
                 :: "r"(dst), "l"(src) : "memory")
#define CP_COMMIT() asm volatile("cp.async.commit_group;" ::: "memory")
#define CP_WAIT2()  asm volatile("cp.async.wait_group 2;" ::: "memory")

// ---------------- fused prep + s kernel -------------------------------------
// blocks [0,3744): f32->bf16 casts (ttab, w1, w2, embed, atab)
// blocks [3744,3748): v[d] = pos_emb_w . pos_feature_w[:,d]
// blocks [3748,4772): s[b,q] attention scalars (128 blocks per batch)
__global__ void prep_s_kernel(const float* __restrict__ ttab,
                              const float* __restrict__ w1,
                              const float* __restrict__ w2,
                              const float* __restrict__ embed,
                              const float* __restrict__ atab,
                              const float* __restrict__ pew,
                              const float* __restrict__ pfw,
                              const float* __restrict__ pos,
                              const int* __restrict__ token)
{
    int blk = blockIdx.x;
    int tid = threadIdx.x;

    if (blk < 3744) {
        int i = blk * 256 + tid;   // float4 index
        const float4* src;
        __nv_bfloat16* dst;
        int off;
        float4 v;
        if (i < 262144) {
            int m = i >> 8;
            v = (m < TROWS) ? ((const float4*)ttab)[i] : make_float4(0.f, 0.f, 0.f, 0.f);
            *(uint2*)(g_A1 + (size_t)i * 4) =
                make_uint2(packbf2(v.x, v.y), packbf2(v.z, v.w));
            return;
        } else if (i < 524288) { src = (const float4*)w1;    dst = g_W1;   off = i - 262144; }
        else if (i < 786432)   { src = (const float4*)w2;    dst = g_W2;   off = i - 524288; }
        else if (i < 827392)   { src = (const float4*)embed; dst = g_embb; off = i - 786432; }
        else                   { src = (const float4*)atab;  dst = g_atb;  off = i - 827392; }
        v = src[off];
        *(uint2*)(dst + (size_t)off * 4) = make_uint2(packbf2(v.x, v.y), packbf2(v.z, v.w));
        return;
    }
    if (blk < 3748) {
        int d = (blk - 3744) * 256 + tid;
        float acc = 0.f;
#pragma unroll 8
        for (int k = 0; k < KK; k++)
            acc += pew[k] * pfw[k * DD + d];
        g_v[d] = acc;
        return;
    }

    // ---- s part: keys in registers, 8 register-resident queries/block ----
    __shared__ float px[LL], py[LL], pz[LL], rr[LL], mm[LL];
    __shared__ float red[8][8][2];
    int sb = blk - 3748;
    int b = sb >> 7;
    int q0 = (sb & 127) * 8;
    int w = tid >> 5, lane = tid & 31;

    for (int j = tid; j < LL; j += 256) {
        float x = pos[(size_t)(b * LL + j) * 3 + 0];
        float y = pos[(size_t)(b * LL + j) * 3 + 1];
        float z = pos[(size_t)(b * LL + j) * 3 + 2];
        px[j] = x; py[j] = y; pz[j] = z;
        float n2 = x * x + y * y + z * z;
        rr[j] = n2 * rsqrtf(fmaxf(n2, 1e-36f));
        mm[j] = (token[b * LL + j] != 0) ? 1.0f : 0.0f;
    }
    __syncthreads();

    float qx[8], qy[8], qz[8];
#pragma unroll
    for (int qq = 0; qq < 8; qq++) {
        qx[qq] = px[q0 + qq]; qy[qq] = py[q0 + qq]; qz[qq] = pz[q0 + qq];
    }
    float se[8], sr[8];
#pragma unroll
    for (int qq = 0; qq < 8; qq++) { se[qq] = 0.f; sr[qq] = 0.f; }

#pragma unroll
    for (int ch = 0; ch < 4; ch++) {
        int j = ch * 256 + w * 32 + lane;
        float kx = px[j], ky = py[j], kz = pz[j];
        float kr = rr[j], km = mm[j];
#pragma unroll
        for (int qq = 0; qq < 8; qq++) {
            float dx = kx - qx[qq], dy = ky - qy[qq], dz = kz - qz[qq];
            float n2 = dx * dx + dy * dy + dz * dz;
            float d = n2 * rsqrtf(fmaxf(n2, 1e-36f));
            float x = __fdividef(SCALING, d + 1.0f);
            float p = fmaf(x, 0.041666667f, 0.16666667f);   // exp Taylor, x<=0.0884
            p = fmaf(x, p, 0.5f);
            p = fmaf(x, p, 1.0f);
            float e = fmaf(x, p, 1.0f);
            float wt = e * km;
            se[qq] += wt;
            sr[qq] = fmaf(wt, kr, sr[qq]);
        }
    }

#pragma unroll
    for (int qq = 0; qq < 8; qq++) {
        float a = se[qq], c = sr[qq];
#pragma unroll
        for (int o = 16; o > 0; o >>= 1) {
            a += __shfl_xor_sync(0xffffffffu, a, o);
            c += __shfl_xor_sync(0xffffffffu, c, o);
        }
        if (lane == 0) { red[w][qq][0] = a; red[w][qq][1] = c; }
    }
    __syncthreads();
    if (tid < 8) {
        float SE = 0.f, SR = 0.f;
#pragma unroll
        for (int ww = 0; ww < 8; ww++) { SE += red[ww][tid][0]; SR += red[ww][tid][1]; }
        g_s[b * LL + q0 + tid] = (mm[q0 + tid] != 0.f) ? (SR / SE) : 0.0f;
    }
}

// ---------------- bf16 GEMM: C = A[M,K] @ W[K,N] (+bias, opt SiLU) ---------
// CTA tile 64x64, 128 threads (4 warps, 2m x 2n), warp tile 32x32,
// K-chunk 32, 4-stage cp.async. 256 CTAs -> 2 per SM, one full wave.
#define PITCH_A 80
#define PITCH_B 144
#define OFF_B 5120
#define STG 9728
__global__ void __launch_bounds__(128, 2)
gemm_mma_kernel(const float* __restrict__ bias, int stage)
{
    extern __shared__ __align__(16) char smem[];

    const __nv_bfloat16* A = stage ? g_Ah : g_A1;
    const __nv_bfloat16* W = stage ? g_W2 : g_W1;

    const int tid = threadIdx.x;
    const int lane = tid & 31;
    const int wid = tid >> 5;
    const int wm = wid & 1;           // 2 warps along M
    const int wn = wid >> 1;          // 2 warps along N
    const int m0 = blockIdx.y * 64;
    const int n0 = blockIdx.x * 64;

    const uint32_t sbase = (uint32_t)__cvta_generic_to_shared(smem);

    uint32_t offA[2];
#pragma unroll
    for (int mf = 0; mf < 2; mf++)
        offA[mf] = (uint32_t)((wm * 32 + mf * 16 + (lane & 15)) * PITCH_A
                              + ((lane >> 4) & 1) * 16);
    const uint32_t offB = (uint32_t)(OFF_B + (lane & 15) * PITCH_B
                                     + (wn * 32 + ((lane >> 4) & 1) * 8) * 2);

    float acc[2][4][4];
#pragma unroll
    for (int i = 0; i < 2; i++)
#pragma unroll
        for (int j = 0; j < 4; j++)
#pragma unroll
            for (int q = 0; q < 4; q++) acc[i][j][q] = 0.f;

    // cp.async: A = 64 rows x 4 x 16B slots (256), B = 32 rows x 8 slots (256)
#define ISSUE(c_)                                                               \
    do {                                                                        \
        uint32_t st = sbase + ((c_) & 3) * STG;                                 \
        int k0 = (c_) * 32;                                                     \
        _Pragma("unroll")                                                       \
        for (int ii = 0; ii < 2; ii++) {                                        \
            int i = tid + ii * 128;                                             \
            int ra = i >> 2, qa = i & 3;                                        \
            CP16(st + ra * PITCH_A + qa * 16,                                   \
                 A + (size_t)(m0 + ra) * DD + k0 + qa * 8);                     \
            int rb = i >> 3, qb = i & 7;                                        \
            CP16(st + OFF_B + rb * PITCH_B + qb * 16,                           \
                 W + (size_t)(k0 + rb) * DD + n0 + qb * 8);                     \
        }                                                                       \
    } while (0)

    ISSUE(0); CP_COMMIT();
    ISSUE(1); CP_COMMIT();
    ISSUE(2); CP_COMMIT();

    for (int c = 0; c < 32; c++) {
        CP_WAIT2();
        __syncthreads();
        const uint32_t sst = sbase + (c & 3) * STG;

#pragma unroll
        for (int kk = 0; kk < 2; kk++) {
            uint32_t ah[2][4], bf[2][4];
#pragma unroll
            for (int mf = 0; mf < 2; mf++)
                ldsm_x4(ah[mf], sst + offA[mf] + kk * 32);
#pragma unroll
            for (int p = 0; p < 2; p++)
                ldsm_x4_t(bf[p], sst + offB + kk * 16 * PITCH_B + p * 32);
#pragma unroll
            for (int mf = 0; mf < 2; mf++)
#pragma unroll
                for (int nf = 0; nf < 4; nf++) {
                    const int p = nf >> 1, ix = (nf & 1) * 2;
                    mma_bf16(acc[mf][nf], ah[mf], bf[p][ix], bf[p][ix + 1]);
                }
        }
        if (c + 3 < 32) ISSUE(c + 3);
        CP_COMMIT();
    }

    // ---- epilogue: bias (+SiLU for stage 0); bf16 outputs both stages ----
#pragma unroll
    for (int mf = 0; mf < 2; mf++) {
#pragma unroll
        for (int nf = 0; nf < 4; nf++) {
            int col = n0 + wn * 32 + nf * 8 + (lane & 3) * 2;
            float2 bb = *(const float2*)(bias + col);
            int r0 = m0 + wm * 32 + mf * 16 + (lane >> 2);
#pragma unroll
            for (int half = 0; half < 2; half++) {
                int r = r0 + half * 8;
                float v0 = acc[mf][nf][2 * half + 0] + bb.x;
                float v1 = acc[mf][nf][2 * half + 1] + bb.y;
                if (stage == 0) {
                    v0 = __fdividef(v0, 1.0f + __expf(-v0));
                    v1 = __fdividef(v1, 1.0f + __expf(-v1));
                    *(uint32_t*)(g_Ah + (size_t)r * DD + col) = packbf2(v0, v1);
                } else {
                    *(uint32_t*)(g_tmlpb + (size_t)r * DD + col) = packbf2(v0, v1);
                }
            }
        }
    }
}

// ---------------- fused epilogue over [B,L,D] (+ padding mask tail) --------
__global__ void epilogue_kernel(const int* __restrict__ token,
                                const int* __restrict__ node_attr,
                                const int* __restrict__ ismol,
                                const int* __restrict__ tstep,
                                float* __restrict__ out,
                                int write_mask)
{
    __shared__ int sidx[8];
    __shared__ int stok, sts, smol;
    __shared__ float ss;
    int bl = blockIdx.x;
    int b = bl >> 10;
    int tid = threadIdx.x;
    if (tid < 8) sidx[tid] = node_attr[bl * 9 + 1 + tid];
    else if (tid == 8) stok = token[bl];
    else if (tid == 9) sts = tstep[bl];
    else if (tid == 10) smol = ismol[b];
    else if (tid == 11) ss = g_s[bl];
    __syncthreads();

    int d = tid * 4;
    float4 acc = bfq(*(const uint2*)(g_embb + (size_t)stok * DD + d));
    float4 t4 = bfq(*(const uint2*)(g_tmlpb + (size_t)sts * DD + d));
    acc.x += t4.x; acc.y += t4.y; acc.z += t4.z; acc.w += t4.w;
    if (smol) {
#pragma unroll
        for (int j = 0; j < 8; j++) {
            float4 a4 = bfq(*(const uint2*)(g_atb + (size_t)sidx[j] * DD + d));
            acc.x += a4.x; acc.y += a4.y; acc.z += a4.z; acc.w += a4.w;
        }
    }
    if (stok != 0) {
        float4 v4 = *(const float4*)(g_v + d);
        float s = ss;
        acc.x += s * v4.x; acc.y += s * v4.y; acc.z += s * v4.z; acc.w += s * v4.w;
    }
    *(float4*)(out + (size_t)bl * DD + d) = acc;

    if (write_mask && tid == 12)
        out[(size_t)BB * LL * DD + bl] = (stok == 0) ? 1.0f : 0.0f;
}

// ---------------------------------------------------------------------------
extern "C" void kernel_launch(void* const* d_in, const int* in_sizes, int n_in,
                              void* d_out, int out_size)
{
    const int*   token     = (const int*)d_in[0];
    const int*   node_attr = (const int*)d_in[1];
    const int*   ismol     = (const int*)d_in[2];
    const float* pos       = (const float*)d_in[3];
    const int*   tstep     = (const int*)d_in[4];
    const float* embed     = (const float*)d_in[5];
    const float* atab      = (const float*)d_in[6];
    const float* ttab      = (const float*)d_in[7];
    const float* w1        = (const float*)d_in[8];
    const float* b1        = (const float*)d_in[9];
    const float* w2        = (const float*)d_in[10];
    const float* b2        = (const float*)d_in[11];
    const float* pew       = (const float*)d_in[12];
    const float* pfw       = (const float*)d_in[13];
    float* out = (float*)d_out;

    const int DSMEM = 4 * STG;   // 38912 bytes
    cudaFuncSetAttribute(gemm_mma_kernel,
                         cudaFuncAttributeMaxDynamicSharedMemorySize, DSMEM);

    // fused prep (bf16 casts + v + s) in one launch
    prep_s_kernel<<<4772, 256>>>(ttab, w1, w2, embed, atab, pew, pfw, pos, token);

    // time MLP via mma.sync bf16 (fp32 accumulate), 64x64 tiles, 2 CTAs/SM
    gemm_mma_kernel<<<dim3(16, 16), 128, DSMEM>>>(b1, 0);
    gemm_mma_kernel<<<dim3(16, 16), 128, DSMEM>>>(b2, 1);

    // fused gather + add epilogue (+mask tail)
    int write_mask = (out_size >= BB * LL * DD + BB * LL) ? 1 : 0;
    epilogue_kernel<<<BB * LL, 256>>>(token, node_attr, ismol, tstep,
                                      out, write_mask);
}